// round 1
// baseline (speedup 1.0000x reference)
#include <cuda_runtime.h>
#include <cstdint>

// Problem: out[256,64] = haar_dwt2(x[256, 262144]) @ W[64, 262144]^T + b[64]
// Factorization: out = x @ W'^T + b, where W' = adjoint-Haar-DWT applied to W rows.
//   t index j = (c, w, p, q)  [c<4 chan, w<4 band, p,q<128]
//   x index i = (c, r, col)   [r,col<256]
//   W'[n][c,r,col] = 0.5*( LL + rs*LH + cs*HL + rs*cs*HH ),
//     rs = (r&1)? -1:+1, cs = (col&1)? -1:+1,  bands read at (c, w, r>>1, col>>1)

#define IN_FEATS (1 << 18)          // 262144
#define BATCH    256
#define NOUT     64
#define KSPLIT   128
#define KC       (IN_FEATS / KSPLIT)  // 2048
#define MB       64
#define KB       16

__device__ float g_Wp[NOUT * IN_FEATS];            // 67 MB scratch: W'
__device__ float g_part[KSPLIT * BATCH * NOUT];    // 8 MB split-K partials

// ---------- packed f32x2 helpers (Blackwell packed fp32 pipe) ----------
__device__ __forceinline__ unsigned long long pack2(float lo, float hi) {
    unsigned long long r;
    asm("mov.b64 %0, {%1, %2};" : "=l"(r) : "f"(lo), "f"(hi));
    return r;
}
__device__ __forceinline__ void unpack2(unsigned long long v, float& lo, float& hi) {
    asm("mov.b64 {%0, %1}, %2;" : "=f"(lo), "=f"(hi) : "l"(v));
}
__device__ __forceinline__ void fma2(unsigned long long& acc,
                                     unsigned long long a, unsigned long long b) {
    asm("fma.rn.f32x2 %0, %1, %2, %0;" : "+l"(acc) : "l"(a), "l"(b));
}

// ---------- Kernel 1: W' = adjoint-DWT(W) ----------
// Each thread produces 4 consecutive W' elements (one float4 store),
// reading float2 from each of the 4 bands (coalesced, L2-friendly).
__global__ __launch_bounds__(256) void k_wtransform(const float* __restrict__ W) {
    int t   = blockIdx.x * 256 + threadIdx.x;
    int idx = t << 2;                       // base output index into W' (n*IN + ...)
    int n    = idx >> 18;
    int rem  = idx & (IN_FEATS - 1);
    int c    = rem >> 16;
    int r    = (rem >> 8) & 255;
    int colb = rem & 255;                   // multiple of 4
    int p = r >> 1, q0 = colb >> 1;         // q0 even

    const float* base = W + ((size_t)n << 18) + (c << 16) + (p << 7) + q0;
    float2 LL = *(const float2*)(base);
    float2 LH = *(const float2*)(base + 16384);
    float2 HL = *(const float2*)(base + 32768);
    float2 HH = *(const float2*)(base + 49152);

    float rs = (r & 1) ? -1.0f : 1.0f;
    float e0 = LL.x + rs * LH.x, f0 = HL.x + rs * HH.x;
    float e1 = LL.y + rs * LH.y, f1 = HL.y + rs * HH.y;

    float4 o;
    o.x = 0.5f * (e0 + f0);   // col parity 0 (cs=+1)
    o.y = 0.5f * (e0 - f0);   // col parity 1 (cs=-1)
    o.z = 0.5f * (e1 + f1);
    o.w = 0.5f * (e1 - f1);
    *(float4*)(g_Wp + idx) = o;
}

// ---------- Kernel 2: split-K GEMM partials (f32x2 packed FMA) ----------
// Block (ks, mt): 64x64 output tile over K chunk of 2048.
// Thread: 4m x 4n micro-tile; accumulators are 8 packed f32x2.
__global__ __launch_bounds__(256) void k_gemm(const float* __restrict__ x) {
    __shared__ float As[KB][68];   // [k][m], stride 68: float4-aligned rows, low-conflict
    __shared__ float Bs[KB][68];   // [k][n]

    int ks = blockIdx.x, mt = blockIdx.y;
    int tid  = threadIdx.x;
    int row  = tid >> 2;           // 0..63 (m for x, n for W')
    int kseg = (tid & 3) << 2;     // 0,4,8,12
    int tx = tid & 15, ty = tid >> 4;

    const float* xp = x    + (size_t)(mt * MB + row) * IN_FEATS + ks * KC + kseg;
    const float* wp = g_Wp + (size_t)row            * IN_FEATS + ks * KC + kseg;

    unsigned long long acc[4][2];
#pragma unroll
    for (int i = 0; i < 4; i++) { acc[i][0] = 0ULL; acc[i][1] = 0ULL; }

    for (int kk = 0; kk < KC; kk += KB) {
        float4 va = *(const float4*)(xp + kk);
        float4 vb = *(const float4*)(wp + kk);
        __syncthreads();
        As[kseg + 0][row] = va.x; As[kseg + 1][row] = va.y;
        As[kseg + 2][row] = va.z; As[kseg + 3][row] = va.w;
        Bs[kseg + 0][row] = vb.x; Bs[kseg + 1][row] = vb.y;
        Bs[kseg + 2][row] = vb.z; Bs[kseg + 3][row] = vb.w;
        __syncthreads();
#pragma unroll
        for (int k = 0; k < KB; k++) {
            float4 a = *(const float4*)&As[k][ty << 2];
            unsigned long long b01 = *(const unsigned long long*)&Bs[k][(tx << 2)];
            unsigned long long b23 = *(const unsigned long long*)&Bs[k][(tx << 2) + 2];
            unsigned long long a0 = pack2(a.x, a.x), a1 = pack2(a.y, a.y);
            unsigned long long a2 = pack2(a.z, a.z), a3 = pack2(a.w, a.w);
            fma2(acc[0][0], a0, b01); fma2(acc[0][1], a0, b23);
            fma2(acc[1][0], a1, b01); fma2(acc[1][1], a1, b23);
            fma2(acc[2][0], a2, b01); fma2(acc[2][1], a2, b23);
            fma2(acc[3][0], a3, b01); fma2(acc[3][1], a3, b23);
        }
    }

    float* pp = g_part + ((size_t)ks * BATCH + mt * MB) * NOUT;
#pragma unroll
    for (int i = 0; i < 4; i++) {
        float4 o;
        unpack2(acc[i][0], o.x, o.y);
        unpack2(acc[i][1], o.z, o.w);
        *(float4*)(pp + (size_t)((ty << 2) + i) * NOUT + (tx << 2)) = o;
    }
}

// ---------- Kernel 3: reduce partials + bias (deterministic) ----------
__global__ __launch_bounds__(256) void k_reduce(const float* __restrict__ bias,
                                                float* __restrict__ out) {
    int t = blockIdx.x * 256 + threadIdx.x;     // 0..16383
    float s = bias[t & (NOUT - 1)];
    const float* p = g_part + t;
#pragma unroll 16
    for (int ks = 0; ks < KSPLIT; ks++)
        s += p[(size_t)ks * BATCH * NOUT];
    out[t] = s;
}

extern "C" void kernel_launch(void* const* d_in, const int* in_sizes, int n_in,
                              void* d_out, int out_size) {
    const float* x = (const float*)d_in[0];
    const float* W = (const float*)d_in[1];
    const float* b = (const float*)d_in[2];

    k_wtransform<<<(NOUT * IN_FEATS / 4) / 256, 256>>>(W);
    k_gemm<<<dim3(KSPLIT, BATCH / MB), 256>>>(x);
    k_reduce<<<(BATCH * NOUT) / 256, 256>>>(b, (float*)d_out);
}

// round 3
// speedup vs baseline: 1.9358x; 1.9358x over previous
#include <cuda_runtime.h>
#include <cuda_bf16.h>
#include <cstdint>

// out[256,64] = haar_dwt2(x[256,262144]) @ W[64,262144]^T + b
// Factorized: out = x @ W'^T + b with W' = adjoint-Haar(W).
// W' is precomputed as bf16 hi/lo planes; GEMM uses mma.sync bf16 (3-term
// split => ~fp32 accuracy) with fp32 accumulators, split-K over 64 chunks.

#define IN_FEATS (1 << 18)            // 262144
#define BATCH    256
#define NOUT     64
#define KSPLIT   64
#define KC       (IN_FEATS / KSPLIT)  // 4096
#define BM       128
#define BN       64
#define BK       32
#define NB       (KC / BK)            // 128 k-blocks per CTA

// smem stage layout (bf16, row stride 40 elems = 80 B, conflict-free frags)
#define RS        40
#define RSB       80
#define AH_OFF    0
#define AL_OFF    (BM * RSB)              // 10240
#define BH_OFF    (2 * BM * RSB)          // 20480
#define BL_OFF    (BH_OFF + BN * RSB)     // 25600
#define STAGE     (BL_OFF + BN * RSB)     // 30720
#define SMEM_ALLOC (2 * STAGE)            // 61440

__device__ __nv_bfloat16 g_Wph[NOUT * IN_FEATS];   // 33.5 MB
__device__ __nv_bfloat16 g_Wpl[NOUT * IN_FEATS];   // 33.5 MB
__device__ float g_part[KSPLIT * BATCH * NOUT];    // 4 MB split-K partials

// ---------------- helpers ----------------
__device__ __forceinline__ uint32_t smem_u32(const void* p) {
    uint32_t a;
    asm("{ .reg .u64 t; cvta.to.shared.u64 t, %1; cvt.u32.u64 %0, t; }"
        : "=r"(a) : "l"(p));
    return a;
}
__device__ __forceinline__ void cp_async16(uint32_t dst, const void* src) {
    asm volatile("cp.async.cg.shared.global [%0], [%1], 16;"
                 :: "r"(dst), "l"(src) : "memory");
}
__device__ __forceinline__ void cp_commit() {
    asm volatile("cp.async.commit_group;" ::: "memory");
}
template <int N>
__device__ __forceinline__ void cp_wait() {
    asm volatile("cp.async.wait_group %0;" :: "n"(N) : "memory");
}
__device__ __forceinline__ uint32_t pkbf2(float a, float b) {
    __nv_bfloat162 t = __floats2bfloat162_rn(a, b);
    return *(uint32_t*)&t;
}
__device__ __forceinline__ void mma_bf16(float* d, const uint32_t* a,
                                         const uint32_t* b) {
    asm volatile(
        "mma.sync.aligned.m16n8k16.row.col.f32.bf16.bf16.f32 "
        "{%0,%1,%2,%3}, {%4,%5,%6,%7}, {%8,%9}, {%0,%1,%2,%3};"
        : "+f"(d[0]), "+f"(d[1]), "+f"(d[2]), "+f"(d[3])
        : "r"(a[0]), "r"(a[1]), "r"(a[2]), "r"(a[3]), "r"(b[0]), "r"(b[1]));
}

// ---------- Kernel 1: W' = adjoint-DWT(W), emitted as bf16 hi/lo ----------
__global__ __launch_bounds__(256) void k_wtransform(const float* __restrict__ W) {
    int t   = blockIdx.x * 256 + threadIdx.x;
    int idx = t << 2;
    int n    = idx >> 18;
    int rem  = idx & (IN_FEATS - 1);
    int c    = rem >> 16;
    int r    = (rem >> 8) & 255;
    int colb = rem & 255;
    int p = r >> 1, q0 = colb >> 1;

    const float* base = W + ((size_t)n << 18) + (c << 16) + (p << 7) + q0;
    float2 LL = *(const float2*)(base);
    float2 LH = *(const float2*)(base + 16384);
    float2 HL = *(const float2*)(base + 32768);
    float2 HH = *(const float2*)(base + 49152);

    float rs = (r & 1) ? -1.0f : 1.0f;
    float e0 = LL.x + rs * LH.x, f0 = HL.x + rs * HH.x;
    float e1 = LL.y + rs * LH.y, f1 = HL.y + rs * HH.y;

    float v0 = 0.5f * (e0 + f0);
    float v1 = 0.5f * (e0 - f0);
    float v2 = 0.5f * (e1 + f1);
    float v3 = 0.5f * (e1 - f1);

    __nv_bfloat16 h0 = __float2bfloat16(v0), h1 = __float2bfloat16(v1);
    __nv_bfloat16 h2 = __float2bfloat16(v2), h3 = __float2bfloat16(v3);
    float l0 = v0 - __bfloat162float(h0), l1 = v1 - __bfloat162float(h1);
    float l2 = v2 - __bfloat162float(h2), l3 = v3 - __bfloat162float(h3);

    uint2 hs, ls;
    hs.x = ((uint32_t)*(uint16_t*)&h0) | ((uint32_t)*(uint16_t*)&h1 << 16);
    hs.y = ((uint32_t)*(uint16_t*)&h2) | ((uint32_t)*(uint16_t*)&h3 << 16);
    ls.x = pkbf2(l0, l1);
    ls.y = pkbf2(l2, l3);
    *(uint2*)(g_Wph + idx) = hs;
    *(uint2*)(g_Wpl + idx) = ls;
}

// ---------- Kernel 2: mma.sync bf16 split-K GEMM ----------
// Grid (KSPLIT, 2). CTA: M=128 (blockIdx.y), N=64, K chunk 4096.
__global__ __launch_bounds__(256) void k_gemm_mma(const float* __restrict__ x) {
    extern __shared__ char sm[];
    const char* smc = sm;
    uint32_t sb = smem_u32(sm);
    int tid = threadIdx.x, lid = tid & 31, wid = tid >> 5;
    int ks = blockIdx.x, mt = blockIdx.y;
    int wm = wid & 3, wn = wid >> 2;          // warp grid 4(m) x 2(n)

    // --- load assignments ---
    // A: thread -> row = tid>>1 (128 rows), 16-col segment (tid&1)
    int arow = tid >> 1, aseg = tid & 1;
    const float* xsrc = x + (size_t)(mt * BM + arow) * IN_FEATS
                          + (size_t)ks * KC + aseg * 16;
    uint32_t a_sts_h = sb + AH_OFF + arow * RSB + aseg * 32;
    uint32_t a_sts_l = a_sts_h + (AL_OFF - AH_OFF);
    // B: thread -> row = tid>>2 (64 rows), 16B chunk (tid&3)
    int brow = tid >> 2, bc = tid & 3;
    const __nv_bfloat16* bhsrc = g_Wph + (size_t)brow * IN_FEATS
                                       + (size_t)ks * KC + bc * 8;
    const __nv_bfloat16* blsrc = g_Wpl + (size_t)brow * IN_FEATS
                                       + (size_t)ks * KC + bc * 8;
    uint32_t b_dst_h = sb + BH_OFF + brow * RSB + bc * 16;
    uint32_t b_dst_l = b_dst_h + (BL_OFF - BH_OFF);

    float acc[2][4][4];
#pragma unroll
    for (int i = 0; i < 2; i++)
#pragma unroll
        for (int j = 0; j < 4; j++)
#pragma unroll
            for (int k = 0; k < 4; k++) acc[i][j][k] = 0.0f;

    // prologue: LDG A(0), cp.async B(0) -> stage 0
    float4 av[4];
#pragma unroll
    for (int i = 0; i < 4; i++) av[i] = *(const float4*)(xsrc + i * 4);
    cp_async16(b_dst_h, bhsrc);
    cp_async16(b_dst_l, blsrc);
    cp_commit();

    // frag base offsets (within a stage), bytes
    int r = lid >> 2, cq = (lid & 3) * 2;
    int a_frag_base = (wm * 32 + r) * RSB + cq * 2;
    int b_frag_base = (wn * 32 + r) * RSB + cq * 2;

    for (int jb = 0; jb < NB; jb++) {
        uint32_t stg = (jb & 1) ? STAGE : 0;

        // convert + STS A(jb) into stage cur
#pragma unroll
        for (int i = 0; i < 4; i++) {
            uint2 h, l;
            h.x = pkbf2(av[i].x, av[i].y);
            h.y = pkbf2(av[i].z, av[i].w);
            __nv_bfloat16 bx = __float2bfloat16(av[i].x);
            __nv_bfloat16 by = __float2bfloat16(av[i].y);
            __nv_bfloat16 bz = __float2bfloat16(av[i].z);
            __nv_bfloat16 bw = __float2bfloat16(av[i].w);
            l.x = pkbf2(av[i].x - __bfloat162float(bx),
                        av[i].y - __bfloat162float(by));
            l.y = pkbf2(av[i].z - __bfloat162float(bz),
                        av[i].w - __bfloat162float(bw));
            asm volatile("st.shared.v2.b32 [%0], {%1,%2};"
                         :: "r"(a_sts_h + stg + i * 8), "r"(h.x), "r"(h.y));
            asm volatile("st.shared.v2.b32 [%0], {%1,%2};"
                         :: "r"(a_sts_l + stg + i * 8), "r"(l.x), "r"(l.y));
        }

        if (jb + 1 < NB) {
            uint32_t nstg = (jb & 1) ? 0 : STAGE;
            cp_async16(b_dst_h + nstg, bhsrc + (jb + 1) * BK);
            cp_async16(b_dst_l + nstg, blsrc + (jb + 1) * BK);
            cp_commit();
            const float* nx = xsrc + (jb + 1) * BK;
#pragma unroll
            for (int i = 0; i < 4; i++) av[i] = *(const float4*)(nx + i * 4);
            cp_wait<1>();
        } else {
            cp_wait<0>();
        }
        __syncthreads();

        // --- MMA on stage cur ---
#pragma unroll
        for (int k0 = 0; k0 < 2; k0++) {
            int kb = k0 * 32;   // 16 cols * 2B
            uint32_t ah[2][4], al[2][4], bh[4][2], bl[4][2];
#pragma unroll
            for (int m = 0; m < 2; m++) {
                const char* p = smc + stg + AH_OFF + a_frag_base + m * 1280 + kb;
                ah[m][0] = *(const uint32_t*)(p);
                ah[m][1] = *(const uint32_t*)(p + 640);
                ah[m][2] = *(const uint32_t*)(p + 16);
                ah[m][3] = *(const uint32_t*)(p + 656);
                const char* q = p + (AL_OFF - AH_OFF);
                al[m][0] = *(const uint32_t*)(q);
                al[m][1] = *(const uint32_t*)(q + 640);
                al[m][2] = *(const uint32_t*)(q + 16);
                al[m][3] = *(const uint32_t*)(q + 656);
            }
#pragma unroll
            for (int n = 0; n < 4; n++) {
                const char* p = smc + stg + BH_OFF + b_frag_base + n * 640 + kb;
                bh[n][0] = *(const uint32_t*)(p);
                bh[n][1] = *(const uint32_t*)(p + 16);
                const char* q = p + (BL_OFF - BH_OFF);
                bl[n][0] = *(const uint32_t*)(q);
                bl[n][1] = *(const uint32_t*)(q + 16);
            }
#pragma unroll
            for (int m = 0; m < 2; m++)
#pragma unroll
                for (int n = 0; n < 4; n++) {
                    mma_bf16(acc[m][n], ah[m], bh[n]);
                    mma_bf16(acc[m][n], ah[m], bl[n]);
                    mma_bf16(acc[m][n], al[m], bh[n]);
                }
        }
        __syncthreads();
    }

    // --- epilogue: write split-K partials ---
#pragma unroll
    for (int m = 0; m < 2; m++) {
#pragma unroll
        for (int n = 0; n < 4; n++) {
            int gm = mt * BM + wm * 32 + m * 16 + r;
            int gn = wn * 32 + n * 8 + cq;
            float* pp = g_part + ((size_t)ks * BATCH + gm) * NOUT + gn;
            *(float2*)(pp)             = make_float2(acc[m][n][0], acc[m][n][1]);
            *(float2*)(pp + 8 * NOUT)  = make_float2(acc[m][n][2], acc[m][n][3]);
        }
    }
}

// ---------- Kernel 3: reduce split-K partials + bias ----------
__global__ __launch_bounds__(256) void k_reduce(const float* __restrict__ bias,
                                                float* __restrict__ out) {
    int t = blockIdx.x * 256 + threadIdx.x;     // 0..16383
    float s = bias[t & (NOUT - 1)];
    const float* p = g_part + t;
#pragma unroll 16
    for (int ks = 0; ks < KSPLIT; ks++)
        s += p[(size_t)ks * BATCH * NOUT];
    out[t] = s;
}

extern "C" void kernel_launch(void* const* d_in, const int* in_sizes, int n_in,
                              void* d_out, int out_size) {
    const float* x = (const float*)d_in[0];
    const float* W = (const float*)d_in[1];
    const float* b = (const float*)d_in[2];

    cudaFuncSetAttribute(k_gemm_mma, cudaFuncAttributeMaxDynamicSharedMemorySize,
                         SMEM_ALLOC);

    k_wtransform<<<(NOUT * IN_FEATS / 4) / 256, 256>>>(W);
    k_gemm_mma<<<dim3(KSPLIT, BATCH / BM), 256, SMEM_ALLOC>>>(x);
    k_reduce<<<(BATCH * NOUT) / 256, 256>>>(b, (float*)d_out);
}

// round 4
// speedup vs baseline: 2.4751x; 1.2786x over previous
#include <cuda_runtime.h>
#include <cuda_fp16.h>
#include <cstdint>

// out[256,64] = haar_dwt2(x[256,262144]) @ W[64,262144]^T + b
// Factorized: out = x @ W'^T + b with W' = adjoint-Haar(W), stored fp16.
// GEMM: mma.sync m16n8k16 fp16, A = exact hi/lo fp16 pair from x (2-term
// product, dropped term ~2^-12), fp32 accum, split-K 64 x 2 M-tiles.

#define IN_FEATS (1 << 18)            // 262144
#define BATCH    256
#define NOUT     64
#define KSPLIT   64
#define KC       (IN_FEATS / KSPLIT)  // 4096
#define BK       32
#define NB       (KC / BK)            // 128
#define BSTRIDE  80                   // B smem row pitch (bytes), conflict-free
#define BSTAGE   (64 * BSTRIDE)       // 5120 B
#define NSTG     4

__device__ __half g_Wp[NOUT * IN_FEATS];           // 33.5 MB  W' fp16
__device__ float  g_part[KSPLIT * BATCH * NOUT];   // 4 MB split-K partials

// ---------------- helpers ----------------
__device__ __forceinline__ uint32_t smem_u32(const void* p) {
    uint32_t a;
    asm("{ .reg .u64 t; cvta.to.shared.u64 t, %1; cvt.u32.u64 %0, t; }"
        : "=r"(a) : "l"(p));
    return a;
}
__device__ __forceinline__ void cp_async16(uint32_t dst, const void* src) {
    asm volatile("cp.async.cg.shared.global [%0], [%1], 16;"
                 :: "r"(dst), "l"(src) : "memory");
}
__device__ __forceinline__ void cp_commit() {
    asm volatile("cp.async.commit_group;" ::: "memory");
}
template <int N>
__device__ __forceinline__ void cp_wait() {
    asm volatile("cp.async.wait_group %0;" :: "n"(N) : "memory");
}
__device__ __forceinline__ void mma_fp16(float* d, const uint32_t* a,
                                         const uint32_t* b) {
    asm volatile(
        "mma.sync.aligned.m16n8k16.row.col.f32.f16.f16.f32 "
        "{%0,%1,%2,%3}, {%4,%5,%6,%7}, {%8,%9}, {%0,%1,%2,%3};"
        : "+f"(d[0]), "+f"(d[1]), "+f"(d[2]), "+f"(d[3])
        : "r"(a[0]), "r"(a[1]), "r"(a[2]), "r"(a[3]), "r"(b[0]), "r"(b[1]));
}
#define LDMX4(r0, r1, r2, r3, addr)                                          \
    asm volatile("ldmatrix.sync.aligned.m8n8.x4.shared.b16 {%0,%1,%2,%3}, [%4];" \
                 : "=r"(r0), "=r"(r1), "=r"(r2), "=r"(r3) : "r"(addr))
__device__ __forceinline__ uint32_t h2u(__half2 h) { return *(uint32_t*)&h; }

// ---------- Kernel 1: W' = adjoint-DWT(W), fp16 output ----------
__global__ __launch_bounds__(256) void k_wtransform(const float* __restrict__ W) {
    int t   = blockIdx.x * 256 + threadIdx.x;
    int idx = t << 2;
    int n    = idx >> 18;
    int rem  = idx & (IN_FEATS - 1);
    int c    = rem >> 16;
    int r    = (rem >> 8) & 255;
    int colb = rem & 255;
    int p = r >> 1, q0 = colb >> 1;

    const float* base = W + ((size_t)n << 18) + (c << 16) + (p << 7) + q0;
    float2 LL = *(const float2*)(base);
    float2 LH = *(const float2*)(base + 16384);
    float2 HL = *(const float2*)(base + 32768);
    float2 HH = *(const float2*)(base + 49152);

    float rs = (r & 1) ? -1.0f : 1.0f;
    float e0 = LL.x + rs * LH.x, f0 = HL.x + rs * HH.x;
    float e1 = LL.y + rs * LH.y, f1 = HL.y + rs * HH.y;

    __half2 h01 = __floats2half2_rn(0.5f * (e0 + f0), 0.5f * (e0 - f0));
    __half2 h23 = __floats2half2_rn(0.5f * (e1 + f1), 0.5f * (e1 - f1));
    uint2 o;
    o.x = h2u(h01);
    o.y = h2u(h23);
    *(uint2*)(g_Wp + idx) = o;
}

// ---------- Kernel 2: mma.sync fp16 split-K GEMM ----------
// Grid (KSPLIT, 2). CTA 256 thr = 8 warps, warp tile 16(m) x 64(n).
// A: direct LDG fp32 -> hi/lo fp16 regs (no smem). B: cp.async 4-stage ring.
__global__ __launch_bounds__(256, 1) void k_gemm_mma(const float* __restrict__ x) {
    __shared__ __align__(128) char bs[NSTG * BSTAGE];
    uint32_t sb = smem_u32(bs);
    int tid = threadIdx.x, l = tid & 31, wid = tid >> 5;
    int ks = blockIdx.x, mt = blockIdx.y;
    int m0 = wid * 16;

    // A load addresses: thread owns rows (m0 + l/4, +8), k-pairs at q, q+8, q+16, q+24
    int r0 = m0 + (l >> 2), q = (l & 3) * 2;
    const float* a0p = x + (size_t)(mt * 128 + r0) * IN_FEATS + (size_t)ks * KC + q;
    const float* a1p = a0p + (size_t)8 * IN_FEATS;

    // B cp.async: thread -> row tid>>2 (64 rows), 16B chunk tid&3
    int brow = tid >> 2, bc = tid & 3;
    const __half* bsrc = g_Wp + (size_t)brow * IN_FEATS + (size_t)ks * KC + bc * 8;
    uint32_t bdst = sb + brow * BSTRIDE + bc * 16;

    // ldmatrix lane address base: tiles (frag f: lanes g<2) rows li, (f+1: g>=2) +8 rows,
    // (g&1) selects k+8 (16B)
    int g = l >> 3, li = l & 7;
    uint32_t lm_base = sb + (uint32_t)(li + (g >> 1) * 8) * BSTRIDE + (g & 1) * 16;

    float acc[8][4];
#pragma unroll
    for (int f = 0; f < 8; f++)
#pragma unroll
        for (int i = 0; i < 4; i++) acc[f][i] = 0.0f;

    float2 Ab[2][8];
#define LDA(jb, d)                                                   \
    do {                                                             \
        const float* p0 = a0p + (jb) * BK;                           \
        const float* p1 = a1p + (jb) * BK;                           \
        (d)[0] = *(const float2*)(p0);      (d)[1] = *(const float2*)(p1);      \
        (d)[2] = *(const float2*)(p0 + 8);  (d)[3] = *(const float2*)(p1 + 8);  \
        (d)[4] = *(const float2*)(p0 + 16); (d)[5] = *(const float2*)(p1 + 16); \
        (d)[6] = *(const float2*)(p0 + 24); (d)[7] = *(const float2*)(p1 + 24); \
    } while (0)

    // prologue: A regs for jb 0,1; B stages 0..2
    LDA(0, Ab[0]);
    LDA(1, Ab[1]);
#pragma unroll
    for (int s = 0; s < NSTG - 1; s++) {
        cp_async16(bdst + s * BSTAGE, bsrc + s * BK);
        cp_commit();
    }

    for (int jb = 0; jb < NB; jb++) {
        cp_wait<NSTG - 2>();
        __syncthreads();

        // refill stage (jb+3)%4 (consumed at jb-1, safe after the sync)
        if (jb + NSTG - 1 < NB)
            cp_async16(bdst + ((jb + NSTG - 1) & (NSTG - 1)) * BSTAGE,
                       bsrc + (jb + NSTG - 1) * BK);
        cp_commit();

        // convert A(jb) to hi/lo fp16 fragments
        uint32_t ah[2][4], al[2][4];
        float2* A = Ab[jb & 1];
#pragma unroll
        for (int k0 = 0; k0 < 2; k0++)
#pragma unroll
            for (int i = 0; i < 4; i++) {
                float2 v = A[k0 * 4 + i];
                __half2 h = __floats2half2_rn(v.x, v.y);
                ah[k0][i] = h2u(h);
                __half2 lo = __floats2half2_rn(v.x - __low2float(h),
                                               v.y - __high2float(h));
                al[k0][i] = h2u(lo);
            }

        // prefetch A(jb+2) into the buffer just consumed
        if (jb + 2 < NB) LDA(jb + 2, Ab[jb & 1]);

        // B fragments via ldmatrix + mma (2 terms)
        uint32_t stg = (jb & (NSTG - 1)) * BSTAGE;
#pragma unroll
        for (int k0 = 0; k0 < 2; k0++) {
#pragma unroll
            for (int fp = 0; fp < 4; fp++) {
                uint32_t b0, b1, b2, b3;
                LDMX4(b0, b1, b2, b3, lm_base + stg + fp * (16 * BSTRIDE) + k0 * 32);
                uint32_t bf0[2] = {b0, b1}, bf1[2] = {b2, b3};
                mma_fp16(acc[fp * 2],     ah[k0], bf0);
                mma_fp16(acc[fp * 2],     al[k0], bf0);
                mma_fp16(acc[fp * 2 + 1], ah[k0], bf1);
                mma_fp16(acc[fp * 2 + 1], al[k0], bf1);
            }
        }
    }

    // epilogue: split-K partials. d-frag: (r0, n..n+1) = d0,d1; (r0+8, ...) = d2,d3
    int gm0 = mt * 128 + r0;
    float* pbase = g_part + ((size_t)ks * BATCH + gm0) * NOUT;
#pragma unroll
    for (int f = 0; f < 8; f++) {
        int n = f * 8 + q;
        *(float2*)(pbase + n)            = make_float2(acc[f][0], acc[f][1]);
        *(float2*)(pbase + 8 * NOUT + n) = make_float2(acc[f][2], acc[f][3]);
    }
}

// ---------- Kernel 3: reduce split-K partials + bias ----------
__global__ __launch_bounds__(256) void k_reduce(const float* __restrict__ bias,
                                                float* __restrict__ out) {
    int t = blockIdx.x * 256 + threadIdx.x;     // 0..16383
    float s = bias[t & (NOUT - 1)];
    const float* p = g_part + t;
#pragma unroll 16
    for (int ks = 0; ks < KSPLIT; ks++)
        s += p[(size_t)ks * BATCH * NOUT];
    out[t] = s;
}

extern "C" void kernel_launch(void* const* d_in, const int* in_sizes, int n_in,
                              void* d_out, int out_size) {
    const float* x = (const float*)d_in[0];
    const float* W = (const float*)d_in[1];
    const float* b = (const float*)d_in[2];

    k_wtransform<<<(NOUT * IN_FEATS / 4) / 256, 256>>>(W);
    k_gemm_mma<<<dim3(KSPLIT, BATCH / 128), 256>>>(x);
    k_reduce<<<(BATCH * NOUT) / 256, 256>>>(b, (float*)d_out);
}